// round 14
// baseline (speedup 1.0000x reference)
#include <cuda_runtime.h>

#define NN 8192
#define MM 2048
#define DD 256
#define DHH 8
#define ROW_CAP 64
#define COL_CAP 128
#define PROJ_BLOCKS 40          // (NN+MM)/256
#define SCAN_BLOCKS 2048
#define SCAN_ITERS 8            // NN*MM/4 / (SCAN_BLOCKS*256)

// ---------------- scratch (static device globals; zero-init at load) ---------
__device__ float g_sx[NN];
__device__ float g_s2[NN];
__device__ float g_se[MM];
__device__ float g_s1[MM];
__device__ int   g_row_cnt[NN];        // zero at entry; re-zeroed in k_out
__device__ int   g_col_cnt[MM];
__device__ __align__(16) int g_row_edges[NN * ROW_CAP];
__device__ int   g_col_nodes[MM * COL_CAP];
// packed per-node record: [sx, 0, s2, 0, WX0..7, pad4] (stride 16 floats)
__device__ __align__(16) float g_npack[NN * 16];
__device__ __align__(16) float g_eacc[MM * DHH];    // zero at entry; re-zeroed in k_enew
__device__ __align__(16) float g_empty_wx[DHH];     // zeroed by proj each replay
__device__ __align__(16) float g_empty_en[DHH];
__device__ __align__(16) float g_xacc[NN * DHH];    // zero at entry; re-zeroed in k_out

__device__ __forceinline__ float leaky(float x) { return x >= 0.f ? x : 0.2f * x; }
// fast ELU: __expf(x)-1 (~6e-8 abs err vs expm1f; global tol is 1e-3)
__device__ __forceinline__ float elu(float x)   { return x > 0.f ? x : __expf(x) - 1.f; }
__device__ __forceinline__ void pdl_wait()    { asm volatile("griddepcontrol.wait;" ::: "memory"); }
__device__ __forceinline__ void pdl_trigger() { asm volatile("griddepcontrol.launch_dependents;" ::: "memory"); }
// vector reduction: 4 floats, one L2 atomic op (sm_90+)
__device__ __forceinline__ void red_add_v4(float* p, float a, float b, float c, float d) {
    asm volatile("red.global.add.v4.f32 [%0], {%1, %2, %3, %4};"
                 :: "l"(p), "f"(a), "f"(b), "f"(c), "f"(d) : "memory");
}

// ---------------- K1: fused projection + H scan (independent block groups) ---
__global__ void k_main(const float* __restrict__ X, const float* __restrict__ E,
                       const float* __restrict__ H, const float* __restrict__ W,
                       const float* __restrict__ ax, const float* __restrict__ ae) {
    if (blockIdx.x >= PROJ_BLOCKS) {
        // ---- scan: H loads PRE-wait (input-only), atomics POST-wait ----
        int t = (blockIdx.x - PROJ_BLOCKS) * blockDim.x + threadIdx.x;
        const int stride = SCAN_BLOCKS * 256;
        const uint4* H4 = reinterpret_cast<const uint4*>(H);
        uint4 v[SCAN_ITERS];
#pragma unroll
        for (int it = 0; it < SCAN_ITERS; it++) v[it] = H4[t + it * stride];

        pdl_wait();        // prior replay's k_out re-zeroed counters

#pragma unroll
        for (int it = 0; it < SCAN_ITERS; it++) {
            uint4 h = v[it];
            if (h.x | h.y | h.z | h.w) {
                int base = (t + it * stride) * 4;
                unsigned c4[4] = {h.x, h.y, h.z, h.w};
#pragma unroll
                for (int c = 0; c < 4; c++) {
                    if (c4[c]) {
                        int lin = base + c;
                        int i = lin >> 11;        // / MM
                        int k = lin & (MM - 1);   // % MM
                        int p = atomicAdd(&g_row_cnt[i], 1);
                        if (p < ROW_CAP) g_row_edges[i * ROW_CAP + p] = k;
                        int q = atomicAdd(&g_col_cnt[k], 1);
                        if (q < COL_CAP) g_col_nodes[k * COL_CAP + q] = i;
                    }
                }
            }
        }
        pdl_trigger();     // publishes complete lists/counts
        return;
    }

    // ---- projection: full compute PRE-wait (inputs only) ----
    __shared__ float sW[DD * DHH];
    __shared__ float sax[2 * DHH], sae[2 * DHH];
    for (int j = threadIdx.x; j < DD * DHH; j += blockDim.x) sW[j] = W[j];
    if (threadIdx.x < 2 * DHH) {
        sax[threadIdx.x] = ax[threadIdx.x];
        sae[threadIdx.x] = ae[threadIdx.x];
    }
    __syncthreads();

    int r = blockIdx.x * blockDim.x + threadIdx.x;   // 0..10239
    const float* src = (r < NN) ? (X + (size_t)r * DD)
                                : (E + (size_t)(r - NN) * DD);
    float acc[DHH];
#pragma unroll
    for (int d = 0; d < DHH; d++) acc[d] = 0.f;

    const float4* Ar = reinterpret_cast<const float4*>(src);
#pragma unroll 4
    for (int j4 = 0; j4 < DD / 4; j4++) {
        float4 x = Ar[j4];
        int j = 4 * j4;
#pragma unroll
        for (int d = 0; d < DHH; d++) acc[d] += x.x * sW[(j + 0) * DHH + d];
#pragma unroll
        for (int d = 0; d < DHH; d++) acc[d] += x.y * sW[(j + 1) * DHH + d];
#pragma unroll
        for (int d = 0; d < DHH; d++) acc[d] += x.z * sW[(j + 2) * DHH + d];
#pragma unroll
        for (int d = 0; d < DHH; d++) acc[d] += x.w * sW[(j + 3) * DHH + d];
    }
    float d1 = 0.f, d2 = 0.f;
    if (r < NN) {
#pragma unroll
        for (int d = 0; d < DHH; d++) {
            d1 += acc[d] * sax[d];          // alpha_x[:dh]
            d2 += acc[d] * sae[DHH + d];    // alpha_e[dh:]
        }
    } else {
#pragma unroll
        for (int d = 0; d < DHH; d++) {
            d1 += acc[d] * sax[DHH + d];    // alpha_x[dh:]
            d2 += acc[d] * sae[d];          // alpha_e[:dh]
        }
    }

    pdl_wait();        // prior replay fully done -> safe to overwrite state

    if (r < DHH) { g_empty_wx[r] = 0.f; g_empty_en[r] = 0.f; }
    if (r < NN) {
        g_sx[r] = d1; g_s2[r] = d2;
        float4* np = reinterpret_cast<float4*>(&g_npack[r * 16]);
        np[0] = make_float4(d1, 0.f, d2, 0.f);
        np[1] = make_float4(acc[0], acc[1], acc[2], acc[3]);
        np[2] = make_float4(acc[4], acc[5], acc[6], acc[7]);
    } else {
        int k = r - NN;
        g_se[k] = d1; g_s1[k] = d2;
    }
    pdl_trigger();     // publishes proj outputs
}

// ---------------- K2: node-parallel rowSum + scatter of E_new contributions --
// 8 lanes per node. eacc[k] += (e1/rowSum)*WX[i] for each incident pair.
__global__ void k_gather() {
    pdl_wait();
    int gid = blockIdx.x * blockDim.x + threadIdx.x;   // NN*8 threads
    int i = gid >> 3, l8 = gid & 7;
    int cnt = min(g_row_cnt[i], ROW_CAP);
    float sxi = g_sx[i];

    int   idx[8];
    float ev[8];
    float s = 0.f;
#pragma unroll
    for (int t = 0; t < 8; t++) {
        int j = l8 + 8 * t;
        bool act = (j < cnt);
        int k = act ? g_row_edges[i * ROW_CAP + j] : 0;
        float ex = act ? __expf(leaky(sxi + g_se[k])) : 0.f;
        idx[t] = act ? k : -1;
        ev[t] = ex;
        s += ex;
    }
    // width-8 butterfly, UNCONDITIONAL (all warp lanes participate)
    s += __shfl_xor_sync(0xffffffffu, s, 4);
    s += __shfl_xor_sync(0xffffffffu, s, 2);
    s += __shfl_xor_sync(0xffffffffu, s, 1);

    if (cnt == 0) {
        if (l8 == 0) {
            const float4* w = reinterpret_cast<const float4*>(&g_npack[i * 16 + 4]);
            float4 w0 = w[0], w1 = w[1];
            red_add_v4(&g_empty_wx[0], w0.x, w0.y, w0.z, w0.w);
            red_add_v4(&g_empty_wx[4], w1.x, w1.y, w1.z, w1.w);
        }
        pdl_trigger();
        return;
    }

    float inv = 1.f / s;
    const float4* np = reinterpret_cast<const float4*>(&g_npack[i * 16]);
    float4 w0 = np[1], w1 = np[2];                     // WX (broadcast across 8 lanes)
#pragma unroll
    for (int t = 0; t < 8; t++) {
        if (idx[t] >= 0) {
            float w = ev[t] * inv;
            float* dst = &g_eacc[idx[t] * DHH];
            red_add_v4(dst,     w * w0.x, w * w0.y, w * w0.z, w * w0.w);
            red_add_v4(dst + 4, w * w1.x, w * w1.y, w * w1.z, w * w1.w);
        }
    }
    pdl_trigger();     // publishes eacc + empty_wx
}

// ---------------- K3: E_new finalize + col softmax + scatter to xacc ---------
// Pre-wait: colS from s2 gathers (k_main data only). Post-wait: read own eacc.
__global__ void __launch_bounds__(256) k_enew() {
    int gid = blockIdx.x * blockDim.x + threadIdx.x;
    int k = gid >> 5;                                 // exactly MM warps
    int lane = gid & 31;
    // ---- pre-wait ----
    int cnt = min(g_col_cnt[k], COL_CAP);
    float s1k = g_s1[k];
    int   iv[4];
    float e2v[4];
    float colS = 0.f;
#pragma unroll
    for (int t = 0; t < 4; t++) {
        int j = lane + 32 * t;
        bool act = (j < cnt);
        int i = act ? g_col_nodes[k * COL_CAP + j] : 0;
        iv[t] = act ? i : -1;
        float e2 = act ? __expf(leaky(s1k + g_s2[i])) : 0.f;
        e2v[t] = e2;
        colS += e2;
    }
#pragma unroll
    for (int off = 16; off > 0; off >>= 1)
        colS += __shfl_xor_sync(0xffffffffu, colS, off);

    pdl_wait();        // k_gather done: eacc + empty_wx final

    const float invM = 1.f / MM;
    float4 ew0 = *reinterpret_cast<const float4*>(&g_empty_wx[0]);
    float4 ew1 = *reinterpret_cast<const float4*>(&g_empty_wx[4]);

    if (cnt == 0) {
        if (lane == 0) {
            red_add_v4(&g_empty_en[0], elu(invM * ew0.x), elu(invM * ew0.y),
                                       elu(invM * ew0.z), elu(invM * ew0.w));
            red_add_v4(&g_empty_en[4], elu(invM * ew1.x), elu(invM * ew1.y),
                                       elu(invM * ew1.z), elu(invM * ew1.w));
        }
        pdl_trigger();
        return;
    }

    // own-edge accumulator (coalesced/uniform 32B)
    float4 a0 = *reinterpret_cast<const float4*>(&g_eacc[k * DHH]);
    float4 a1 = *reinterpret_cast<const float4*>(&g_eacc[k * DHH + 4]);
    float en[DHH];
    en[0] = elu(a0.x + invM * ew0.x); en[1] = elu(a0.y + invM * ew0.y);
    en[2] = elu(a0.z + invM * ew0.z); en[3] = elu(a0.w + invM * ew0.w);
    en[4] = elu(a1.x + invM * ew1.x); en[5] = elu(a1.y + invM * ew1.y);
    en[6] = elu(a1.z + invM * ew1.z); en[7] = elu(a1.w + invM * ew1.w);

    float invColS = __fdividef(1.f, colS);
#pragma unroll
    for (int t = 0; t < 4; t++) {
        if (iv[t] >= 0) {
            float* dst = &g_xacc[iv[t] * DHH];
            float w = e2v[t] * invColS;
            red_add_v4(dst,     w * en[0], w * en[1], w * en[2], w * en[3]);
            red_add_v4(dst + 4, w * en[4], w * en[5], w * en[6], w * en[7]);
        }
    }
    // restore eacc zero-invariant (this warp owns edge k; k_gather is done)
    if (lane == 0) {
        *reinterpret_cast<float4*>(&g_eacc[k * DHH])     = make_float4(0.f, 0.f, 0.f, 0.f);
        *reinterpret_cast<float4*>(&g_eacc[k * DHH + 4]) = make_float4(0.f, 0.f, 0.f, 0.f);
    }
    pdl_trigger();     // publishes xacc + empty_en
}

// ---------------- K4: epilogue (2 elems/thread) + cleanup --------------------
__global__ void k_out(float* __restrict__ out) {
    pdl_wait();
    const int HALF = NN * DHH / 2;                     // 32768
    int gid = blockIdx.x * blockDim.x + threadIdx.x;   // HALF threads
    int g2 = gid + HALF;
    const float invN = 1.f / NN;
    float xa0 = g_xacc[gid];
    float xa1 = g_xacc[g2];
    float en0 = g_empty_en[gid & 7];
    float en1 = g_empty_en[g2 & 7];
    out[gid] = elu(xa0 + invN * en0);
    out[g2]  = elu(xa1 + invN * en1);
    // ---- restore zero-invariants for next replay ----
    g_xacc[gid] = 0.f;
    g_xacc[g2]  = 0.f;
    if (gid < NN) g_row_cnt[gid] = 0;
    if (gid < MM) g_col_cnt[gid] = 0;
    pdl_trigger();     // publishes re-zeroed state (next k_main waits on this)
}

// -----------------------------------------------------------------------------
extern "C" void kernel_launch(void* const* d_in, const int* in_sizes, int n_in,
                              void* d_out, int out_size) {
    const float* X  = (const float*)d_in[0];
    const float* E  = (const float*)d_in[1];
    const float* H  = (const float*)d_in[2];
    const float* W  = (const float*)d_in[3];
    const float* ax = (const float*)d_in[4];
    const float* ae = (const float*)d_in[5];
    float* out = (float*)d_out;

    cudaLaunchAttribute attr;
    attr.id = cudaLaunchAttributeProgrammaticStreamSerialization;
    attr.val.programmaticStreamSerializationAllowed = 1;

    cudaLaunchConfig_t cfg = {};
    cfg.blockDim = dim3(256);
    cfg.dynamicSmemBytes = 0;
    cfg.stream = 0;
    cfg.attrs = &attr;
    cfg.numAttrs = 1;

    cfg.gridDim = dim3(PROJ_BLOCKS + SCAN_BLOCKS);
    cudaLaunchKernelEx(&cfg, k_main, X, E, H, W, ax, ae);

    cfg.gridDim = dim3(NN * 8 / 256);
    cudaLaunchKernelEx(&cfg, k_gather);

    cfg.gridDim = dim3(MM * 32 / 256);
    cudaLaunchKernelEx(&cfg, k_enew);

    cfg.gridDim = dim3(NN * DHH / 2 / 256);
    cudaLaunchKernelEx(&cfg, k_out, out);
}